// round 1
// baseline (speedup 1.0000x reference)
#include <cuda_runtime.h>
#include <cuda_bf16.h>

// Problem constants (fixed shapes per reference)
#define CC 9
#define HH 180
#define WW 240
#define BB 8
#define NN 100000
#define HW (HH * WW)              // 43200
#define NUM_VOXELS (2 * CC * HW * BB)  // 6220800

// Piecewise-linear table of the scalar MLP f(s), s in [-1, 1]
#define TM 65536
__device__ float g_table[TM];

__device__ __forceinline__ float lrelu(float v) {
    // leaky_relu(v, 0.1): for v<0, 0.1v > v; for v>=0, v >= 0.1v
    return fmaxf(v, 0.1f * v);
}

// ---------------------------------------------------------------------------
// Kernel 1: zero the output (poisoned to 0xAA by harness)
// ---------------------------------------------------------------------------
__global__ void zero_out_kernel(float4* __restrict__ out, int n4) {
    int i = blockIdx.x * blockDim.x + threadIdx.x;
    int stride = gridDim.x * blockDim.x;
    for (; i < n4; i += stride)
        out[i] = make_float4(0.f, 0.f, 0.f, 0.f);
}

// ---------------------------------------------------------------------------
// Kernel 2: build f(s) table. One thread per sample point.
// MLP: h1 = lrelu(s*w1 + b1) [100]; h2 = lrelu(h1@w2 + b2) [100]; f = h2@w3 + b3
// w2 staged in shared, rows padded to 104 floats so float4 loads are 16B-aligned.
// ---------------------------------------------------------------------------
__global__ __launch_bounds__(128) void build_table_kernel(
    const float* __restrict__ w1, const float* __restrict__ b1,
    const float* __restrict__ w2, const float* __restrict__ b2,
    const float* __restrict__ w3, const float* __restrict__ b3)
{
    __shared__ float sw2[100 * 104];
    __shared__ float sw1[100], sb1[100], sw3[100], sb2[100];

    int tid = threadIdx.x;
    for (int i = tid; i < 100 * 100; i += blockDim.x) {
        int r = i / 100, c = i - r * 100;
        sw2[r * 104 + c] = w2[i];
    }
    if (tid < 100) {
        sw1[tid] = w1[tid];
        sb1[tid] = b1[tid];
        sw3[tid] = w3[tid];
        sb2[tid] = b2[tid];
    }
    __syncthreads();

    int k = blockIdx.x * blockDim.x + tid;
    if (k >= TM) return;

    float s = -1.0f + 2.0f * (float)k / (float)(TM - 1);

    float h1[100];
#pragma unroll
    for (int j = 0; j < 100; j++) {
        float v = fmaf(s, sw1[j], sb1[j]);
        h1[j] = lrelu(v);
    }

    float out = b3[0];
    for (int j = 0; j < 100; j += 4) {
        float a0 = sb2[j + 0];
        float a1 = sb2[j + 1];
        float a2 = sb2[j + 2];
        float a3 = sb2[j + 3];
#pragma unroll
        for (int i = 0; i < 100; i++) {
            float4 w = *reinterpret_cast<const float4*>(&sw2[i * 104 + j]);
            float h = h1[i];
            a0 = fmaf(h, w.x, a0);
            a1 = fmaf(h, w.y, a1);
            a2 = fmaf(h, w.z, a2);
            a3 = fmaf(h, w.w, a3);
        }
        out = fmaf(lrelu(a0), sw3[j + 0], out);
        out = fmaf(lrelu(a1), sw3[j + 1], out);
        out = fmaf(lrelu(a2), sw3[j + 2], out);
        out = fmaf(lrelu(a3), sw3[j + 3], out);
    }
    g_table[k] = out;
}

// ---------------------------------------------------------------------------
// Kernel 3: scatter. One thread per event; 9 bins; lerp table; atomicAdd.
// Flat voxel index  x + W*y + HW*c + HW*C*p + HW*C*2*b  equals the flat index
// of the concatenated output [B, 2C, H, W], so scatter directly into d_out.
// ---------------------------------------------------------------------------
__global__ __launch_bounds__(256) void scatter_kernel(
    const float* __restrict__ t, const int* __restrict__ x,
    const int* __restrict__ y, const int* __restrict__ p,
    float* __restrict__ out, int total)
{
    int e = blockIdx.x * blockDim.x + threadIdx.x;
    if (e >= total) return;

    float tf = t[e];
    int b = e / NN;
    int base = x[e] + WW * y[e] + HW * CC * p[e] + HW * CC * 2 * b;

    const float scale = (float)(TM - 1) * 0.5f;

#pragma unroll
    for (int i = 0; i < CC; i++) {
        float s = tf - (float)i * 0.125f;   // i / (C-1), C-1 = 8
        float fi = (s + 1.0f) * scale;
        int i0 = (int)fi;
        i0 = max(0, min(i0, TM - 2));
        float fr = fi - (float)i0;
        float f0 = g_table[i0];
        float f1 = g_table[i0 + 1];
        float f = fmaf(f1 - f0, fr, f0);
        int idx = base + i * HW;
        // clip as in reference (never actually triggers for these shapes)
        idx = max(0, min(idx, NUM_VOXELS - 1));
        atomicAdd(out + idx, tf * f);
    }
}

// ---------------------------------------------------------------------------
// Launch
// metadata order: t, w1, b1, w2, b2, w3, b3, x, y, p
// ---------------------------------------------------------------------------
extern "C" void kernel_launch(void* const* d_in, const int* in_sizes, int n_in,
                              void* d_out, int out_size)
{
    const float* t  = (const float*)d_in[0];
    const float* w1 = (const float*)d_in[1];
    const float* b1 = (const float*)d_in[2];
    const float* w2 = (const float*)d_in[3];
    const float* b2 = (const float*)d_in[4];
    const float* w3 = (const float*)d_in[5];
    const float* b3 = (const float*)d_in[6];
    const int*   x  = (const int*)d_in[7];
    const int*   y  = (const int*)d_in[8];
    const int*   p  = (const int*)d_in[9];
    float* out = (float*)d_out;

    int total = in_sizes[0];          // B*N = 800000
    int n4 = out_size / 4;            // 6220800 / 4

    zero_out_kernel<<<592, 256>>>((float4*)out, n4);
    build_table_kernel<<<TM / 128, 128>>>(w1, b1, w2, b2, w3, b3);
    scatter_kernel<<<(total + 255) / 256, 256>>>(t, x, y, p, out, total);
}

// round 2
// speedup vs baseline: 1.5660x; 1.5660x over previous
#include <cuda_runtime.h>
#include <cuda_bf16.h>

// Problem constants (fixed shapes per reference)
#define CC 9
#define HH 180
#define WW 240
#define BB 8
#define NN 100000
#define HW (HH * WW)                   // 43200
#define NUM_VOXELS (2 * CC * HW * BB)  // 6220800

// Piecewise-linear table of the scalar MLP f(s), s in [-1, 1].
// MLP is piecewise-linear (LeakyReLU net on scalar input): lerp is exact
// between kinks; kink error ~ dslope*h -> ~2e-6 at TM=8192 (measured 2.7e-7
// at TM=65536, scales linearly with cell width).
#define TM 8192
__device__ float g_table[TM];

#define BUILD_BLOCKS (TM / 128)   // 64
#define ZERO_BLOCKS  1984

__device__ __forceinline__ float lrelu(float v) {
    return fmaxf(v, 0.1f * v);    // leaky_relu slope 0.1
}

// ---------------------------------------------------------------------------
// Fused kernel: blocks [0, BUILD_BLOCKS) build the f(s) table (one thread per
// sample, w2 staged in shared with rows padded to 104 floats for aligned
// LDS.128 broadcasts); remaining blocks zero the poisoned output.
// The two halves are independent and overlap across SMs.
// ---------------------------------------------------------------------------
__global__ __launch_bounds__(128) void fused_init_kernel(
    float4* __restrict__ out4, int n4,
    const float* __restrict__ w1, const float* __restrict__ b1,
    const float* __restrict__ w2, const float* __restrict__ b2,
    const float* __restrict__ w3, const float* __restrict__ b3)
{
    __shared__ float sw2[100 * 104];
    __shared__ float sw1[100], sb1[100], sw3[100], sb2[100];

    int tid = threadIdx.x;

    if (blockIdx.x >= BUILD_BLOCKS) {
        // ---- zero path ----
        int i = (blockIdx.x - BUILD_BLOCKS) * blockDim.x + tid;
        int stride = ZERO_BLOCKS * blockDim.x;
        float4 z = make_float4(0.f, 0.f, 0.f, 0.f);
        for (; i < n4; i += stride)
            out4[i] = z;
        return;
    }

    // ---- table-build path ----
    for (int i = tid; i < 100 * 100; i += blockDim.x) {
        int r = i / 100, c = i - r * 100;
        sw2[r * 104 + c] = w2[i];
    }
    if (tid < 100) {
        sw1[tid] = w1[tid];
        sb1[tid] = b1[tid];
        sw3[tid] = w3[tid];
        sb2[tid] = b2[tid];
    }
    __syncthreads();

    int k = blockIdx.x * blockDim.x + tid;   // < TM by construction

    float s = -1.0f + 2.0f * (float)k / (float)(TM - 1);

    float h1[100];
#pragma unroll
    for (int j = 0; j < 100; j++)
        h1[j] = lrelu(fmaf(s, sw1[j], sb1[j]));

    float out = b3[0];
    for (int j = 0; j < 100; j += 4) {
        float a0 = sb2[j + 0];
        float a1 = sb2[j + 1];
        float a2 = sb2[j + 2];
        float a3 = sb2[j + 3];
#pragma unroll
        for (int i = 0; i < 100; i++) {
            float4 w = *reinterpret_cast<const float4*>(&sw2[i * 104 + j]);
            float h = h1[i];
            a0 = fmaf(h, w.x, a0);
            a1 = fmaf(h, w.y, a1);
            a2 = fmaf(h, w.z, a2);
            a3 = fmaf(h, w.w, a3);
        }
        out = fmaf(lrelu(a0), sw3[j + 0], out);
        out = fmaf(lrelu(a1), sw3[j + 1], out);
        out = fmaf(lrelu(a2), sw3[j + 2], out);
        out = fmaf(lrelu(a3), sw3[j + 3], out);
    }
    g_table[k] = out;
}

// ---------------------------------------------------------------------------
// Scatter: one thread per event; 9 bins; table lerp; RED.ADD into d_out.
// Flat voxel index x + W*y + HW*c + HW*C*p + HW*C*2*b equals the flat index
// of the concatenated output [B, 2C, H, W], so scatter directly into d_out.
// Table is 32KB -> L1-resident on every SM.
// ---------------------------------------------------------------------------
__global__ __launch_bounds__(256) void scatter_kernel(
    const float* __restrict__ t, const int* __restrict__ x,
    const int* __restrict__ y, const int* __restrict__ p,
    float* __restrict__ out, int total)
{
    int e = blockIdx.x * blockDim.x + threadIdx.x;
    if (e >= total) return;

    float tf = t[e];
    int b = e / NN;
    int base = x[e] + WW * y[e] + HW * CC * p[e] + HW * CC * 2 * b;

    const float scale = (float)(TM - 1) * 0.5f;

#pragma unroll
    for (int i = 0; i < CC; i++) {
        float s = tf - (float)i * 0.125f;     // i/(C-1), C-1 = 8
        float fi = (s + 1.0f) * scale;
        int i0 = (int)fi;
        i0 = max(0, min(i0, TM - 2));
        float fr = fi - (float)i0;
        float f0 = g_table[i0];
        float f1 = g_table[i0 + 1];
        float f = fmaf(f1 - f0, fr, f0);
        int idx = base + i * HW;
        idx = max(0, min(idx, NUM_VOXELS - 1));  // reference clip (no-op here)
        atomicAdd(out + idx, tf * f);
    }
}

// ---------------------------------------------------------------------------
// Launch.  metadata order: t, w1, b1, w2, b2, w3, b3, x, y, p
// ---------------------------------------------------------------------------
extern "C" void kernel_launch(void* const* d_in, const int* in_sizes, int n_in,
                              void* d_out, int out_size)
{
    const float* t  = (const float*)d_in[0];
    const float* w1 = (const float*)d_in[1];
    const float* b1 = (const float*)d_in[2];
    const float* w2 = (const float*)d_in[3];
    const float* b2 = (const float*)d_in[4];
    const float* w3 = (const float*)d_in[5];
    const float* b3 = (const float*)d_in[6];
    const int*   x  = (const int*)d_in[7];
    const int*   y  = (const int*)d_in[8];
    const int*   p  = (const int*)d_in[9];
    float* out = (float*)d_out;

    int total = in_sizes[0];          // B*N = 800000
    int n4 = out_size / 4;            // 1555200 float4s

    fused_init_kernel<<<BUILD_BLOCKS + ZERO_BLOCKS, 128>>>(
        (float4*)out, n4, w1, b1, w2, b2, w3, b3);
    scatter_kernel<<<(total + 255) / 256, 256>>>(t, x, y, p, out, total);
}

// round 3
// speedup vs baseline: 1.6547x; 1.0567x over previous
#include <cuda_runtime.h>
#include <cuda_bf16.h>

// Problem constants (fixed shapes per reference)
#define CC 9
#define HH 180
#define WW 240
#define BB 8
#define NN 100000
#define HW (HH * WW)                   // 43200
#define NUM_VOXELS (2 * CC * HW * BB)  // 6220800

// Piecewise-linear table of the scalar MLP f(s), s in [-1, 1].
// LeakyReLU net on a scalar input is piecewise-linear: lerp is exact between
// kinks; kink error ~ dslope*h. Measured 1.08e-6 rel_err at TM=8192 ->
// ~2.2e-6 at TM=4096, still ~450x under the 1e-3 gate.
#define TM 4096

// j dimension padded 100 -> 112 = 4 groups of 28 (28 % 4 == 0 for LDS.128)
#define JP 112
#define JG 28

__device__ float g_table[TM];

#define BUILD_BLOCKS ((TM * 4) / 128)   // 128 blocks
#define ZERO_BLOCKS  1024

__device__ __forceinline__ float lrelu(float v) {
    return fmaxf(v, 0.1f * v);    // leaky_relu slope 0.1
}

// ---------------------------------------------------------------------------
// Fused init kernel.
// Blocks [0, BUILD_BLOCKS): build the f(s) table. 4 threads per sample, each
//   owning a 28-wide slice of the padded 112-neuron hidden layer; partials
//   reduced with shfl_xor. h1_i computed on the fly (no per-thread h1 array).
// Blocks [BUILD_BLOCKS, ...): zero the poisoned output (DRAM-bound, overlaps
//   the build across SMs).
// ---------------------------------------------------------------------------
__global__ __launch_bounds__(128, 1) void fused_init_kernel(
    float4* __restrict__ out4, int n4,
    const float* __restrict__ w1, const float* __restrict__ b1,
    const float* __restrict__ w2, const float* __restrict__ b2,
    const float* __restrict__ w3, const float* __restrict__ b3)
{
    __shared__ float sw2[100 * JP];            // [i][j], j zero-padded to 112
    __shared__ float sw1[100], sb1[100];
    __shared__ float sb2[JP], sw3[JP];

    int tid = threadIdx.x;

    if (blockIdx.x >= BUILD_BLOCKS) {
        // ---- zero path ----
        int i = (blockIdx.x - BUILD_BLOCKS) * blockDim.x + tid;
        int stride = ZERO_BLOCKS * blockDim.x;
        float4 z = make_float4(0.f, 0.f, 0.f, 0.f);
        for (; i < n4; i += stride)
            out4[i] = z;
        return;
    }

    // ---- stage weights (zero-pad j in [100,112)) ----
    for (int idx = tid; idx < 100 * JP; idx += blockDim.x) {
        int r = idx / JP, c = idx - r * JP;
        sw2[idx] = (c < 100) ? w2[r * 100 + c] : 0.0f;
    }
    if (tid < 100) { sw1[tid] = w1[tid]; sb1[tid] = b1[tid]; }
    if (tid < JP)  {
        sb2[tid] = (tid < 100) ? b2[tid] : 0.0f;
        sw3[tid] = (tid < 100) ? w3[tid] : 0.0f;
    }
    __syncthreads();

    int g  = blockIdx.x * blockDim.x + tid;    // global thread
    int k  = g >> 2;                           // sample index, < TM
    int jt = g & 3;                            // j-group within sample
    int j0 = jt * JG;

    float s = -1.0f + 2.0f * (float)k / (float)(TM - 1);

    // accumulators for this thread's 28 j's
    float acc[JG];
#pragma unroll
    for (int c = 0; c < JG; c++) acc[c] = sb2[j0 + c];

#pragma unroll 4
    for (int i = 0; i < 100; i++) {
        float h = lrelu(fmaf(s, sw1[i], sb1[i]));
        const float4* wrow = reinterpret_cast<const float4*>(&sw2[i * JP + j0]);
#pragma unroll
        for (int q = 0; q < JG / 4; q++) {
            float4 w = wrow[q];
            acc[4 * q + 0] = fmaf(h, w.x, acc[4 * q + 0]);
            acc[4 * q + 1] = fmaf(h, w.y, acc[4 * q + 1]);
            acc[4 * q + 2] = fmaf(h, w.z, acc[4 * q + 2]);
            acc[4 * q + 3] = fmaf(h, w.w, acc[4 * q + 3]);
        }
    }

    float partial = 0.0f;
#pragma unroll
    for (int c = 0; c < JG; c++)
        partial = fmaf(lrelu(acc[c]), sw3[j0 + c], partial);

    // reduce across the 4 threads of this sample (lane groups of 4, aligned)
    partial += __shfl_xor_sync(0xffffffffu, partial, 1);
    partial += __shfl_xor_sync(0xffffffffu, partial, 2);

    if (jt == 0)
        g_table[k] = partial + b3[0];
}

// ---------------------------------------------------------------------------
// Scatter: one thread per event; 9 bins; table lerp; RED.ADD into d_out.
// Flat voxel index x + W*y + HW*c + HW*C*p + HW*C*2*b equals the flat index
// of the concatenated output [B, 2C, H, W], so scatter directly into d_out.
// Table is 16KB -> L1-resident on every SM.
// ---------------------------------------------------------------------------
__global__ __launch_bounds__(256) void scatter_kernel(
    const float* __restrict__ t, const int* __restrict__ x,
    const int* __restrict__ y, const int* __restrict__ p,
    float* __restrict__ out, int total)
{
    int e = blockIdx.x * blockDim.x + threadIdx.x;
    if (e >= total) return;

    float tf = t[e];
    int b = e / NN;
    int base = x[e] + WW * y[e] + HW * CC * p[e] + HW * CC * 2 * b;

    const float scale = (float)(TM - 1) * 0.5f;

#pragma unroll
    for (int i = 0; i < CC; i++) {
        float s = tf - (float)i * 0.125f;     // i/(C-1), C-1 = 8
        float fi = (s + 1.0f) * scale;
        int i0 = (int)fi;
        i0 = max(0, min(i0, TM - 2));
        float fr = fi - (float)i0;
        float f0 = g_table[i0];
        float f1 = g_table[i0 + 1];
        float f = fmaf(f1 - f0, fr, f0);
        int idx = base + i * HW;
        idx = max(0, min(idx, NUM_VOXELS - 1));  // reference clip (no-op here)
        atomicAdd(out + idx, tf * f);
    }
}

// ---------------------------------------------------------------------------
// Launch.  metadata order: t, w1, b1, w2, b2, w3, b3, x, y, p
// ---------------------------------------------------------------------------
extern "C" void kernel_launch(void* const* d_in, const int* in_sizes, int n_in,
                              void* d_out, int out_size)
{
    const float* t  = (const float*)d_in[0];
    const float* w1 = (const float*)d_in[1];
    const float* b1 = (const float*)d_in[2];
    const float* w2 = (const float*)d_in[3];
    const float* b2 = (const float*)d_in[4];
    const float* w3 = (const float*)d_in[5];
    const float* b3 = (const float*)d_in[6];
    const int*   x  = (const int*)d_in[7];
    const int*   y  = (const int*)d_in[8];
    const int*   p  = (const int*)d_in[9];
    float* out = (float*)d_out;

    int total = in_sizes[0];          // B*N = 800000
    int n4 = out_size / 4;            // 1555200 float4s

    fused_init_kernel<<<BUILD_BLOCKS + ZERO_BLOCKS, 128>>>(
        (float4*)out, n4, w1, b1, w2, b2, w3, b3);
    scatter_kernel<<<(total + 255) / 256, 256>>>(t, x, y, p, out, total);
}

// round 4
// speedup vs baseline: 1.7124x; 1.0348x over previous
#include <cuda_runtime.h>
#include <cuda_bf16.h>

// Problem constants (fixed shapes per reference)
#define CC 9
#define HH 180
#define WW 240
#define BB 8
#define NN 100000
#define HW (HH * WW)                   // 43200
#define NUM_VOXELS (2 * CC * HW * BB)  // 6220800

// Piecewise-linear table of the scalar MLP f(s), s in [-1, 1].
// LeakyReLU net on a scalar input is piecewise-linear: lerp is exact between
// kinks; measured rel_err 3.2e-6 at TM=4096 — ~300x under the 1e-3 gate.
#define TM 4096

// j dimension padded 100 -> 112 = 4 groups of 28 (28 % 4 == 0 for LDS.128)
#define JP 112
#define JG 28

__device__ float g_table[TM];

#define BUILD_BLOCKS ((TM * 4) / 128)   // 128 blocks

__device__ __forceinline__ float lrelu(float v) {
    return fmaxf(v, 0.1f * v);    // leaky_relu slope 0.1
}

// ---------------------------------------------------------------------------
// Table build: 4 threads per sample, each owning a 28-wide slice of the
// padded 112-neuron hidden layer; partials reduced with shfl_xor.
// h1_i computed on the fly. ~3 us at 128 blocks.
// ---------------------------------------------------------------------------
__global__ __launch_bounds__(128) void build_table_kernel(
    const float* __restrict__ w1, const float* __restrict__ b1,
    const float* __restrict__ w2, const float* __restrict__ b2,
    const float* __restrict__ w3, const float* __restrict__ b3)
{
    __shared__ float sw2[100 * JP];            // [i][j], j zero-padded to 112
    __shared__ float sw1[100], sb1[100];
    __shared__ float sb2[JP], sw3[JP];

    int tid = threadIdx.x;

    // stage weights (zero-pad j in [100,112))
    for (int idx = tid; idx < 100 * JP; idx += blockDim.x) {
        int r = idx / JP, c = idx - r * JP;
        sw2[idx] = (c < 100) ? w2[r * 100 + c] : 0.0f;
    }
    if (tid < 100) { sw1[tid] = w1[tid]; sb1[tid] = b1[tid]; }
    if (tid < JP)  {
        sb2[tid] = (tid < 100) ? b2[tid] : 0.0f;
        sw3[tid] = (tid < 100) ? w3[tid] : 0.0f;
    }
    __syncthreads();

    int g  = blockIdx.x * blockDim.x + tid;    // global thread
    int k  = g >> 2;                           // sample index, < TM
    int jt = g & 3;                            // j-group within sample
    int j0 = jt * JG;

    float s = -1.0f + 2.0f * (float)k / (float)(TM - 1);

    float acc[JG];
#pragma unroll
    for (int c = 0; c < JG; c++) acc[c] = sb2[j0 + c];

#pragma unroll 4
    for (int i = 0; i < 100; i++) {
        float h = lrelu(fmaf(s, sw1[i], sb1[i]));
        const float4* wrow = reinterpret_cast<const float4*>(&sw2[i * JP + j0]);
#pragma unroll
        for (int q = 0; q < JG / 4; q++) {
            float4 w = wrow[q];
            acc[4 * q + 0] = fmaf(h, w.x, acc[4 * q + 0]);
            acc[4 * q + 1] = fmaf(h, w.y, acc[4 * q + 1]);
            acc[4 * q + 2] = fmaf(h, w.z, acc[4 * q + 2]);
            acc[4 * q + 3] = fmaf(h, w.w, acc[4 * q + 3]);
        }
    }

    float partial = 0.0f;
#pragma unroll
    for (int c = 0; c < JG; c++)
        partial = fmaf(lrelu(acc[c]), sw3[j0 + c], partial);

    // reduce across the 4 threads of this sample (aligned lane quads)
    partial += __shfl_xor_sync(0xffffffffu, partial, 1);
    partial += __shfl_xor_sync(0xffffffffu, partial, 2);

    if (jt == 0)
        g_table[k] = partial + b3[0];
}

// ---------------------------------------------------------------------------
// Scatter: one thread per event; 9 bins; table lerp; RED.ADD into d_out.
// Flat voxel index x + W*y + HW*c + HW*C*p + HW*C*2*b equals the flat index
// of the concatenated output [B, 2C, H, W], so scatter directly into d_out.
// Table is 16KB -> L1-resident on every SM.
// ---------------------------------------------------------------------------
__global__ __launch_bounds__(256) void scatter_kernel(
    const float* __restrict__ t, const int* __restrict__ x,
    const int* __restrict__ y, const int* __restrict__ p,
    float* __restrict__ out, int total)
{
    int e = blockIdx.x * blockDim.x + threadIdx.x;
    if (e >= total) return;

    float tf = t[e];
    int b = e / NN;
    int base = x[e] + WW * y[e] + HW * CC * p[e] + HW * CC * 2 * b;

    const float scale = (float)(TM - 1) * 0.5f;

#pragma unroll
    for (int i = 0; i < CC; i++) {
        float s = tf - (float)i * 0.125f;     // i/(C-1), C-1 = 8
        float fi = (s + 1.0f) * scale;
        int i0 = (int)fi;
        i0 = max(0, min(i0, TM - 2));
        float fr = fi - (float)i0;
        float f0 = g_table[i0];
        float f1 = g_table[i0 + 1];
        float f = fmaf(f1 - f0, fr, f0);
        int idx = base + i * HW;
        idx = max(0, min(idx, NUM_VOXELS - 1));  // reference clip (no-op here)
        atomicAdd(out + idx, tf * f);
    }
}

// ---------------------------------------------------------------------------
// Launch.  metadata order: t, w1, b1, w2, b2, w3, b3, x, y, p
// ---------------------------------------------------------------------------
extern "C" void kernel_launch(void* const* d_in, const int* in_sizes, int n_in,
                              void* d_out, int out_size)
{
    const float* t  = (const float*)d_in[0];
    const float* w1 = (const float*)d_in[1];
    const float* b1 = (const float*)d_in[2];
    const float* w2 = (const float*)d_in[3];
    const float* b2 = (const float*)d_in[4];
    const float* w3 = (const float*)d_in[5];
    const float* b3 = (const float*)d_in[6];
    const int*   x  = (const int*)d_in[7];
    const int*   y  = (const int*)d_in[8];
    const int*   p  = (const int*)d_in[9];
    float* out = (float*)d_out;

    int total = in_sizes[0];          // B*N = 800000

    // Zero the poisoned output via a graph memset node (legacy stream).
    cudaMemsetAsync(out, 0, (size_t)out_size * sizeof(float), 0);

    build_table_kernel<<<BUILD_BLOCKS, 128>>>(w1, b1, w2, b2, w3, b3);
    scatter_kernel<<<(total + 255) / 256, 256>>>(t, x, y, p, out, total);
}

// round 6
// speedup vs baseline: 1.9314x; 1.1279x over previous
#include <cuda_runtime.h>
#include <cuda_bf16.h>

// Problem constants (fixed shapes per reference)
#define CC 9
#define HH 180
#define WW 240
#define BB 8
#define NN 100000
#define HW (HH * WW)                   // 43200
#define NUM_VOXELS (2 * CC * HW * BB)  // 6220800
#define NCELLS (BB * 2 * HW)           // 691200 (pixel x polarity x batch)
#define CPAD 12                        // bins padded 9 -> 12 (16B alignment)

// Piecewise-linear table of the scalar MLP f(s), s in [-1, 1].
// LeakyReLU net on a scalar input is piecewise-linear: lerp exact between
// kinks; measured rel_err 3.2e-6 at TM=4096 — ~300x under the 1e-3 gate.
#define TM 4096

// j dimension padded 100 -> 112 = 4 groups of 28 (28 % 4 == 0 for LDS.128)
#define JP 112
#define JG 28

__device__ float g_table[TM];
__device__ float g_scratch[(size_t)NCELLS * CPAD];   // 33.2 MB bin-contiguous scratch

#define BUILD_BLOCKS ((TM * 4) / 128)   // 128 blocks

__device__ __forceinline__ float lrelu(float v) {
    return fmaxf(v, 0.1f * v);    // leaky_relu slope 0.1
}

// ---------------------------------------------------------------------------
// Table build: 4 threads per sample, each owning a 28-wide slice of the
// padded 112-neuron hidden layer; partials reduced with shfl_xor.
// ---------------------------------------------------------------------------
__global__ __launch_bounds__(128) void build_table_kernel(
    const float* __restrict__ w1, const float* __restrict__ b1,
    const float* __restrict__ w2, const float* __restrict__ b2,
    const float* __restrict__ w3, const float* __restrict__ b3)
{
    __shared__ float sw2[100 * JP];            // [i][j], j zero-padded to 112
    __shared__ float sw1[100], sb1[100];
    __shared__ float sb2[JP], sw3[JP];

    int tid = threadIdx.x;

    for (int idx = tid; idx < 100 * JP; idx += blockDim.x) {
        int r = idx / JP, c = idx - r * JP;
        sw2[idx] = (c < 100) ? w2[r * 100 + c] : 0.0f;
    }
    if (tid < 100) { sw1[tid] = w1[tid]; sb1[tid] = b1[tid]; }
    if (tid < JP)  {
        sb2[tid] = (tid < 100) ? b2[tid] : 0.0f;
        sw3[tid] = (tid < 100) ? w3[tid] : 0.0f;
    }
    __syncthreads();

    int g  = blockIdx.x * blockDim.x + tid;    // global thread
    int k  = g >> 2;                           // sample index, < TM
    int jt = g & 3;                            // j-group within sample
    int j0 = jt * JG;

    float s = -1.0f + 2.0f * (float)k / (float)(TM - 1);

    float acc[JG];
#pragma unroll
    for (int c = 0; c < JG; c++) acc[c] = sb2[j0 + c];

#pragma unroll 4
    for (int i = 0; i < 100; i++) {
        float h = lrelu(fmaf(s, sw1[i], sb1[i]));
        const float4* wrow = reinterpret_cast<const float4*>(&sw2[i * JP + j0]);
#pragma unroll
        for (int q = 0; q < JG / 4; q++) {
            float4 w = wrow[q];
            acc[4 * q + 0] = fmaf(h, w.x, acc[4 * q + 0]);
            acc[4 * q + 1] = fmaf(h, w.y, acc[4 * q + 1]);
            acc[4 * q + 2] = fmaf(h, w.z, acc[4 * q + 2]);
            acc[4 * q + 3] = fmaf(h, w.w, acc[4 * q + 3]);
        }
    }

    float partial = 0.0f;
#pragma unroll
    for (int c = 0; c < JG; c++)
        partial = fmaf(lrelu(acc[c]), sw3[j0 + c], partial);

    partial += __shfl_xor_sync(0xffffffffu, partial, 1);
    partial += __shfl_xor_sync(0xffffffffu, partial, 2);

    if (jt == 0)
        g_table[k] = partial + b3[0];
}

// ---------------------------------------------------------------------------
// Scatter: one thread per event. 9 bin-values computed via table lerp, then
// accumulated into bin-CONTIGUOUS scratch with 2x red.v4 + 1 scalar RED
// (3 lanes/event instead of 9, all in one 128B line).
// cell = x + W*y + HW*(p + 2*b); scratch[cell][bin].
// ---------------------------------------------------------------------------
__global__ __launch_bounds__(256) void scatter_kernel(
    const float* __restrict__ t, const int* __restrict__ x,
    const int* __restrict__ y, const int* __restrict__ p,
    int total)
{
    int e = blockIdx.x * blockDim.x + threadIdx.x;
    if (e >= total) return;

    float tf = t[e];
    int b = e / NN;
    int cell = x[e] + WW * y[e] + HW * (p[e] + 2 * b);
    float* dst = g_scratch + (size_t)cell * CPAD;

    const float scale = (float)(TM - 1) * 0.5f;

    float v[9];
#pragma unroll
    for (int i = 0; i < CC; i++) {
        float s = tf - (float)i * 0.125f;     // i/(C-1), C-1 = 8
        float fi = (s + 1.0f) * scale;
        int i0 = (int)fi;
        i0 = max(0, min(i0, TM - 2));
        float fr = fi - (float)i0;
        float f0 = g_table[i0];
        float f1 = g_table[i0 + 1];
        v[i] = tf * fmaf(f1 - f0, fr, f0);
    }

    asm volatile("red.global.add.v4.f32 [%0], {%1,%2,%3,%4};"
                 :: "l"(dst), "f"(v[0]), "f"(v[1]), "f"(v[2]), "f"(v[3])
                 : "memory");
    asm volatile("red.global.add.v4.f32 [%0], {%1,%2,%3,%4};"
                 :: "l"(dst + 4), "f"(v[4]), "f"(v[5]), "f"(v[6]), "f"(v[7])
                 : "memory");
    atomicAdd(dst + 8, v[8]);
}

// ---------------------------------------------------------------------------
// Transpose: scratch[cell][c] -> out[(q*C + c)*HW + pix], q = cell/HW.
// q = p + 2b == 2b + p, so (q*C + c)*HW + pix is exactly the reference's
// flat voxel index / concatenated output layout. Coalesced 48B reads,
// 9 coalesced plane stores. Writes EVERY output element (no d_out zeroing).
// ---------------------------------------------------------------------------
__global__ __launch_bounds__(256) void transpose_kernel(float* __restrict__ out)
{
    int cell = blockIdx.x * blockDim.x + threadIdx.x;   // < NCELLS exactly
    const float4* src = reinterpret_cast<const float4*>(g_scratch + (size_t)cell * CPAD);
    float4 a = src[0];
    float4 c4 = src[1];
    float c8 = g_scratch[(size_t)cell * CPAD + 8];

    int q   = cell / HW;
    int pix = cell - q * HW;
    float* o = out + (size_t)q * CC * HW + pix;

    o[0 * HW] = a.x;  o[1 * HW] = a.y;  o[2 * HW] = a.z;  o[3 * HW] = a.w;
    o[4 * HW] = c4.x; o[5 * HW] = c4.y; o[6 * HW] = c4.z; o[7 * HW] = c4.w;
    o[8 * HW] = c8;
}

// ---------------------------------------------------------------------------
// Launch.  metadata order: t, w1, b1, w2, b2, w3, b3, x, y, p
// ---------------------------------------------------------------------------
extern "C" void kernel_launch(void* const* d_in, const int* in_sizes, int n_in,
                              void* d_out, int out_size)
{
    const float* t  = (const float*)d_in[0];
    const float* w1 = (const float*)d_in[1];
    const float* b1 = (const float*)d_in[2];
    const float* w2 = (const float*)d_in[3];
    const float* b2 = (const float*)d_in[4];
    const float* w3 = (const float*)d_in[5];
    const float* b3 = (const float*)d_in[6];
    const int*   x  = (const int*)d_in[7];
    const int*   y  = (const int*)d_in[8];
    const int*   p  = (const int*)d_in[9];
    float* out = (float*)d_out;

    int total = in_sizes[0];          // B*N = 800000

    // Zero the scratch accumulator (graph memset node). d_out needs no
    // zeroing: transpose writes every element.
    void* sp = nullptr;
    cudaGetSymbolAddress(&sp, g_scratch);
    cudaMemsetAsync(sp, 0, (size_t)NCELLS * CPAD * sizeof(float), 0);

    build_table_kernel<<<BUILD_BLOCKS, 128>>>(w1, b1, w2, b2, w3, b3);
    scatter_kernel<<<(total + 255) / 256, 256>>>(t, x, y, p, total);
    transpose_kernel<<<NCELLS / 256, 256>>>(out);
}

// round 7
// speedup vs baseline: 1.9859x; 1.0282x over previous
#include <cuda_runtime.h>
#include <cuda_bf16.h>

// Problem constants (fixed shapes per reference)
#define CC 9
#define HH 180
#define WW 240
#define BB 8
#define NN 100000
#define HW (HH * WW)                   // 43200
#define NUM_VOXELS (2 * CC * HW * BB)  // 6220800
#define NCELLS (BB * 2 * HW)           // 691200 (pixel x polarity x batch)
#define CPAD 12                        // bins padded 9 -> 12 (16B alignment)

// Piecewise-linear table of the scalar MLP f(s), s in [-1, 1].
// LeakyReLU net on a scalar input is piecewise-linear: lerp exact between
// kinks; measured rel_err 3.2e-6 at TM=4096 — ~300x under the 1e-3 gate.
#define TM 4096

__device__ float g_table[TM];
__device__ float g_scratch[(size_t)NCELLS * CPAD];   // 33.2 MB bin-contiguous scratch

__device__ __forceinline__ float lrelu(float v) {
    return fmaxf(v, 0.1f * v);    // leaky_relu slope 0.1
}

// ---------------------------------------------------------------------------
// Table build: ONE WARP PER SAMPLE. Lane l owns hidden cols 4l..4l+3
// (lanes 25-31 predicated off). Per i: h broadcast from smem (LDS.64 of
// interleaved {b1,w1}), one LDG.128 of the w2 quad (40KB, L1-resident since
// every warp reads identical addresses), 4 FMA. Warp-reduce at the end.
// 512 blocks x 256 threads -> ~7 warps/SMSP, latency fully hidden.
// ---------------------------------------------------------------------------
#define BT_THREADS 256
#define BT_WPB (BT_THREADS / 32)                 // 8 samples per block
#define BUILD_BLOCKS (TM / BT_WPB)               // 512 blocks

__global__ __launch_bounds__(BT_THREADS) void build_table_kernel(
    const float* __restrict__ w1, const float* __restrict__ b1,
    const float* __restrict__ w2, const float* __restrict__ b2,
    const float* __restrict__ w3, const float* __restrict__ b3)
{
    __shared__ float2 s_bw1[100];                // {b1[i], w1[i]} pairs

    int tid  = threadIdx.x;
    int lane = tid & 31;
    int wid  = tid >> 5;

    if (tid < 100) s_bw1[tid] = make_float2(b1[tid], w1[tid]);
    __syncthreads();

    int k = blockIdx.x * BT_WPB + wid;           // sample index, < TM
    float s = -1.0f + 2.0f * (float)k / (float)(TM - 1);

    int j0 = lane * 4;
    bool active = (j0 < 100);                    // lanes 0..24

    float a0 = 0.f, a1 = 0.f, a2 = 0.f, a3 = 0.f;
    if (active) {
        float4 bb = *reinterpret_cast<const float4*>(b2 + j0);
        a0 = bb.x; a1 = bb.y; a2 = bb.z; a3 = bb.w;
    }

#pragma unroll 4
    for (int i = 0; i < 100; i++) {
        float2 bw = s_bw1[i];                    // broadcast
        float h = lrelu(fmaf(s, bw.y, bw.x));
        if (active) {
            float4 w = *reinterpret_cast<const float4*>(w2 + i * 100 + j0);
            a0 = fmaf(h, w.x, a0);
            a1 = fmaf(h, w.y, a1);
            a2 = fmaf(h, w.z, a2);
            a3 = fmaf(h, w.w, a3);
        }
    }

    float part = 0.f;
    if (active) {
        float4 w3v = *reinterpret_cast<const float4*>(w3 + j0);
        part = lrelu(a0) * w3v.x + lrelu(a1) * w3v.y
             + lrelu(a2) * w3v.z + lrelu(a3) * w3v.w;
    }

    // butterfly reduce over the warp
    part += __shfl_xor_sync(0xffffffffu, part, 16);
    part += __shfl_xor_sync(0xffffffffu, part, 8);
    part += __shfl_xor_sync(0xffffffffu, part, 4);
    part += __shfl_xor_sync(0xffffffffu, part, 2);
    part += __shfl_xor_sync(0xffffffffu, part, 1);

    if (lane == 0)
        g_table[k] = part + b3[0];
}

// ---------------------------------------------------------------------------
// Scatter: one thread per event. 9 bin-values via table lerp, accumulated
// into bin-CONTIGUOUS scratch with 2x red.v4 + 1 scalar RED (3 lanes/event,
// one 128B line). cell = x + W*y + HW*(p + 2*b).
// ---------------------------------------------------------------------------
__global__ __launch_bounds__(256) void scatter_kernel(
    const float* __restrict__ t, const int* __restrict__ x,
    const int* __restrict__ y, const int* __restrict__ p,
    int total)
{
    int e = blockIdx.x * blockDim.x + threadIdx.x;
    if (e >= total) return;

    float tf = t[e];
    int b = e / NN;
    int cell = x[e] + WW * y[e] + HW * (p[e] + 2 * b);
    float* dst = g_scratch + (size_t)cell * CPAD;

    const float scale = (float)(TM - 1) * 0.5f;

    float v[9];
#pragma unroll
    for (int i = 0; i < CC; i++) {
        float s = tf - (float)i * 0.125f;     // i/(C-1), C-1 = 8
        float fi = (s + 1.0f) * scale;
        int i0 = (int)fi;
        i0 = max(0, min(i0, TM - 2));
        float fr = fi - (float)i0;
        float f0 = g_table[i0];
        float f1 = g_table[i0 + 1];
        v[i] = tf * fmaf(f1 - f0, fr, f0);
    }

    asm volatile("red.global.add.v4.f32 [%0], {%1,%2,%3,%4};"
                 :: "l"(dst), "f"(v[0]), "f"(v[1]), "f"(v[2]), "f"(v[3])
                 : "memory");
    asm volatile("red.global.add.v4.f32 [%0], {%1,%2,%3,%4};"
                 :: "l"(dst + 4), "f"(v[4]), "f"(v[5]), "f"(v[6]), "f"(v[7])
                 : "memory");
    atomicAdd(dst + 8, v[8]);
}

// ---------------------------------------------------------------------------
// Transpose: scratch[cell][c] -> out[(q*C + c)*HW + pix], q = cell/HW.
// q = p + 2b, so (q*C + c)*HW + pix is exactly the reference's flat voxel
// index / concatenated output layout. Writes EVERY output element.
// ---------------------------------------------------------------------------
__global__ __launch_bounds__(256) void transpose_kernel(float* __restrict__ out)
{
    int cell = blockIdx.x * blockDim.x + threadIdx.x;   // < NCELLS exactly
    const float4* src = reinterpret_cast<const float4*>(g_scratch + (size_t)cell * CPAD);
    float4 a = src[0];
    float4 c4 = src[1];
    float c8 = g_scratch[(size_t)cell * CPAD + 8];

    int q   = cell / HW;
    int pix = cell - q * HW;
    float* o = out + (size_t)q * CC * HW + pix;

    o[0 * HW] = a.x;  o[1 * HW] = a.y;  o[2 * HW] = a.z;  o[3 * HW] = a.w;
    o[4 * HW] = c4.x; o[5 * HW] = c4.y; o[6 * HW] = c4.z; o[7 * HW] = c4.w;
    o[8 * HW] = c8;
}

// ---------------------------------------------------------------------------
// Launch.  metadata order: t, w1, b1, w2, b2, w3, b3, x, y, p
// ---------------------------------------------------------------------------
extern "C" void kernel_launch(void* const* d_in, const int* in_sizes, int n_in,
                              void* d_out, int out_size)
{
    const float* t  = (const float*)d_in[0];
    const float* w1 = (const float*)d_in[1];
    const float* b1 = (const float*)d_in[2];
    const float* w2 = (const float*)d_in[3];
    const float* b2 = (const float*)d_in[4];
    const float* w3 = (const float*)d_in[5];
    const float* b3 = (const float*)d_in[6];
    const int*   x  = (const int*)d_in[7];
    const int*   y  = (const int*)d_in[8];
    const int*   p  = (const int*)d_in[9];
    float* out = (float*)d_out;

    int total = in_sizes[0];          // B*N = 800000

    // Zero the scratch accumulator (graph memset node). d_out needs no
    // zeroing: transpose writes every element.
    void* sp = nullptr;
    cudaGetSymbolAddress(&sp, g_scratch);
    cudaMemsetAsync(sp, 0, (size_t)NCELLS * CPAD * sizeof(float), 0);

    build_table_kernel<<<BUILD_BLOCKS, BT_THREADS>>>(w1, b1, w2, b2, w3, b3);
    scatter_kernel<<<(total + 255) / 256, 256>>>(t, x, y, p, total);
    transpose_kernel<<<NCELLS / 256, 256>>>(out);
}

// round 8
// speedup vs baseline: 1.9961x; 1.0052x over previous
#include <cuda_runtime.h>
#include <cuda_bf16.h>

// Problem constants (fixed shapes per reference)
#define CC 9
#define HH 180
#define WW 240
#define BB 8
#define NN 100000
#define HW (HH * WW)                   // 43200
#define NUM_VOXELS (2 * CC * HW * BB)  // 6220800
#define NCELLS (BB * 2 * HW)           // 691200 (pixel x polarity x batch)
#define CPAD 12                        // bins padded 9 -> 12 (16B alignment)

// Piecewise-linear table of the scalar MLP f(s), s in [-1, 1].
// LeakyReLU net on scalar input is piecewise-linear; lerp error is linear in
// cell width (measured: 2.7e-7 @65536, 1.08e-6 @8192, 3.2e-6 @4096).
// TM=1024 -> ~1.3e-5, 77x under the 1e-3 gate.
#define TM 1024

#define JP 104                          // w2 row stride in smem (16B-aligned quads)

__device__ float g_table[TM];
// Zero-initialized at module load; transpose_kernel re-zeroes it after
// reading, so it is zero at the start of every kernel_launch/graph replay.
__device__ float g_scratch[(size_t)NCELLS * CPAD];   // 33.2 MB

__device__ __forceinline__ float lrelu(float v) {
    return fmaxf(v, 0.1f * v);    // leaky_relu slope 0.1
}

// ---------------------------------------------------------------------------
// Table build: ONE WARP PER SAMPLE, w2 staged in SHARED (no global loads in
// the hot loop -> no lockstep L2-latency serialization). Lane l owns hidden
// cols 4l..4l+3 (lanes 25-31 predicated off). Per i: broadcast LDS.64 of
// {b1,w1}, one LDS.128 of the w2 quad, 4 FMA. Butterfly-reduce at the end.
// 128 blocks x 8 warps; ~900 instrs/warp, smem latency covered by unroll.
// ---------------------------------------------------------------------------
#define BT_THREADS 256
#define BT_WPB (BT_THREADS / 32)                 // 8 samples per block
#define BUILD_BLOCKS (TM / BT_WPB)               // 128 blocks

__global__ __launch_bounds__(BT_THREADS) void build_table_kernel(
    const float* __restrict__ w1, const float* __restrict__ b1,
    const float* __restrict__ w2, const float* __restrict__ b2,
    const float* __restrict__ w3, const float* __restrict__ b3)
{
    __shared__ float  sw2[100 * JP];             // [i][j], quad-aligned rows
    __shared__ float2 s_bw1[100];                // {b1[i], w1[i]}

    int tid  = threadIdx.x;
    int lane = tid & 31;
    int wid  = tid >> 5;

    // stage w2 as float4s (global rows are 400B, 16B-aligned)
    for (int f = tid; f < 2500; f += BT_THREADS) {
        float4 v = reinterpret_cast<const float4*>(w2)[f];
        int r = f / 25, c = f - r * 25;
        *reinterpret_cast<float4*>(&sw2[r * JP + c * 4]) = v;
    }
    if (tid < 100) s_bw1[tid] = make_float2(b1[tid], w1[tid]);
    __syncthreads();

    int k = blockIdx.x * BT_WPB + wid;           // sample index, < TM
    float s = -1.0f + 2.0f * (float)k / (float)(TM - 1);

    int j0 = lane * 4;
    bool active = (lane < 25);

    float a0 = 0.f, a1 = 0.f, a2 = 0.f, a3 = 0.f;
    if (active) {
        float4 bb = *reinterpret_cast<const float4*>(b2 + j0);
        a0 = bb.x; a1 = bb.y; a2 = bb.z; a3 = bb.w;
    }

#pragma unroll 4
    for (int i = 0; i < 100; i++) {
        float2 bw = s_bw1[i];                    // broadcast
        float h = lrelu(fmaf(s, bw.y, bw.x));
        if (active) {
            float4 w = *reinterpret_cast<const float4*>(&sw2[i * JP + j0]);
            a0 = fmaf(h, w.x, a0);
            a1 = fmaf(h, w.y, a1);
            a2 = fmaf(h, w.z, a2);
            a3 = fmaf(h, w.w, a3);
        }
    }

    float part = 0.f;
    if (active) {
        float4 w3v = *reinterpret_cast<const float4*>(w3 + j0);
        part = lrelu(a0) * w3v.x + lrelu(a1) * w3v.y
             + lrelu(a2) * w3v.z + lrelu(a3) * w3v.w;
    }

    part += __shfl_xor_sync(0xffffffffu, part, 16);
    part += __shfl_xor_sync(0xffffffffu, part, 8);
    part += __shfl_xor_sync(0xffffffffu, part, 4);
    part += __shfl_xor_sync(0xffffffffu, part, 2);
    part += __shfl_xor_sync(0xffffffffu, part, 1);

    if (lane == 0)
        g_table[k] = part + b3[0];
}

// ---------------------------------------------------------------------------
// Scatter: one thread per event. 9 bin-values via table lerp, accumulated
// into bin-CONTIGUOUS scratch with 2x red.v4 + 1 scalar RED (3 lanes/event,
// one 128B line). cell = x + W*y + HW*(p + 2*b).
// ---------------------------------------------------------------------------
__global__ __launch_bounds__(256) void scatter_kernel(
    const float* __restrict__ t, const int* __restrict__ x,
    const int* __restrict__ y, const int* __restrict__ p,
    int total)
{
    int e = blockIdx.x * blockDim.x + threadIdx.x;
    if (e >= total) return;

    float tf = t[e];
    int b = e / NN;
    int cell = x[e] + WW * y[e] + HW * (p[e] + 2 * b);
    float* dst = g_scratch + (size_t)cell * CPAD;

    const float scale = (float)(TM - 1) * 0.5f;

    float v[9];
#pragma unroll
    for (int i = 0; i < CC; i++) {
        float s = tf - (float)i * 0.125f;     // i/(C-1), C-1 = 8
        float fi = (s + 1.0f) * scale;
        int i0 = (int)fi;
        i0 = max(0, min(i0, TM - 2));
        float fr = fi - (float)i0;
        float f0 = g_table[i0];
        float f1 = g_table[i0 + 1];
        v[i] = tf * fmaf(f1 - f0, fr, f0);
    }

    asm volatile("red.global.add.v4.f32 [%0], {%1,%2,%3,%4};"
                 :: "l"(dst), "f"(v[0]), "f"(v[1]), "f"(v[2]), "f"(v[3])
                 : "memory");
    asm volatile("red.global.add.v4.f32 [%0], {%1,%2,%3,%4};"
                 :: "l"(dst + 4), "f"(v[4]), "f"(v[5]), "f"(v[6]), "f"(v[7])
                 : "memory");
    atomicAdd(dst + 8, v[8]);
}

// ---------------------------------------------------------------------------
// Transpose + scratch reset: scratch[cell][c] -> out[(q*C + c)*HW + pix],
// q = cell/HW = p + 2b, exactly the reference's concatenated output layout.
// After reading, the cell is zeroed so the NEXT launch/replay starts from a
// clean scratch (replaces a 33MB memset node on the critical path).
// ---------------------------------------------------------------------------
__global__ __launch_bounds__(256) void transpose_kernel(float* __restrict__ out)
{
    int cell = blockIdx.x * blockDim.x + threadIdx.x;   // < NCELLS exactly
    float4* src = reinterpret_cast<float4*>(g_scratch + (size_t)cell * CPAD);
    float4 a  = src[0];
    float4 c4 = src[1];
    float4 c8 = src[2];   // .x = bin 8, rest padding

    float4 z = make_float4(0.f, 0.f, 0.f, 0.f);
    src[0] = z; src[1] = z; src[2] = z;

    int q   = cell / HW;
    int pix = cell - q * HW;
    float* o = out + (size_t)q * CC * HW + pix;

    o[0 * HW] = a.x;  o[1 * HW] = a.y;  o[2 * HW] = a.z;  o[3 * HW] = a.w;
    o[4 * HW] = c4.x; o[5 * HW] = c4.y; o[6 * HW] = c4.z; o[7 * HW] = c4.w;
    o[8 * HW] = c8.x;
}

// ---------------------------------------------------------------------------
// Launch.  metadata order: t, w1, b1, w2, b2, w3, b3, x, y, p
// ---------------------------------------------------------------------------
extern "C" void kernel_launch(void* const* d_in, const int* in_sizes, int n_in,
                              void* d_out, int out_size)
{
    const float* t  = (const float*)d_in[0];
    const float* w1 = (const float*)d_in[1];
    const float* b1 = (const float*)d_in[2];
    const float* w2 = (const float*)d_in[3];
    const float* b2 = (const float*)d_in[4];
    const float* w3 = (const float*)d_in[5];
    const float* b3 = (const float*)d_in[6];
    const int*   x  = (const int*)d_in[7];
    const int*   y  = (const int*)d_in[8];
    const int*   p  = (const int*)d_in[9];
    float* out = (float*)d_out;

    int total = in_sizes[0];          // B*N = 800000

    // Scratch is zero: zero-initialized at load, re-zeroed by transpose_kernel
    // at the end of every launch. No memset node needed.
    build_table_kernel<<<BUILD_BLOCKS, BT_THREADS>>>(w1, b1, w2, b2, w3, b3);
    scatter_kernel<<<(total + 255) / 256, 256>>>(t, x, y, p, total);
    transpose_kernel<<<NCELLS / 256, 256>>>(out);
}